// round 3
// baseline (speedup 1.0000x reference)
#include <cuda_runtime.h>
#include <cstddef>

#define BATCH 4096
#define LDIM 64
#define DDIM 256
#define MDIM 20
#define RT 128      // rows per pass1 block
#define CHUNK 64    // d-elems per chunk
#define NCH (DDIM / CHUNK)
#define XST 68      // padded chunk row stride (floats): 68 mod 32 = 4 -> conflict-free LDS.128
#define R2 32

typedef unsigned long long u64;

// ---------------- f32x2 helpers ----------------
__device__ __forceinline__ u64 ffma2(u64 a, u64 b, u64 c) {
    u64 d;
    asm("fma.rn.f32x2 %0, %1, %2, %3;" : "=l"(d) : "l"(a), "l"(b), "l"(c));
    return d;
}
__device__ __forceinline__ u64 pack2(float x, float y) {
    u64 r;
    asm("mov.b64 %0, {%1, %2};" : "=l"(r) : "f"(x), "f"(y));
    return r;
}
__device__ __forceinline__ float2 unpack2(u64 a) {
    float2 f;
    asm("mov.b64 {%0, %1}, %2;" : "=f"(f.x), "=f"(f.y) : "l"(a));
    return f;
}

// ---------------- scratch ----------------
__device__ float g_Wt[3 * MDIM * DDIM];             // transposed weights [proj][m][d]
__device__ float g_qs[(size_t)LDIM * BATCH * MDIM]; // [l][b][m]
__device__ float g_kvs[LDIM * MDIM * MDIM];
__device__ float g_ks_sum[LDIM * MDIM];
__device__ float g_vs_sum[LDIM * MDIM];
__device__ float g_scal[4];                         // sum_q, ssq_q, sum_k, ssq_k
__device__ float g_P[(size_t)LDIM * MDIM * DDIM];   // kvs @ Wp
__device__ float g_C[LDIM * DDIM];                  // vs_sum @ Wp

// ---------------- kernel 0: zero reductions + transpose weights ----------------
__global__ __launch_bounds__(256) void k_init(const float* __restrict__ Wk,
                                              const float* __restrict__ Wq,
                                              const float* __restrict__ Wv) {
    int i = blockIdx.x * 256 + threadIdx.x;
    if (i < 3 * MDIM * DDIM) {
        int p = i / (MDIM * DDIM);
        int rem = i % (MDIM * DDIM);
        int m = rem / DDIM, d = rem % DDIM;
        const float* W = (p == 0) ? Wk : ((p == 1) ? Wq : Wv);
        g_Wt[i] = W[d * MDIM + m];
    }
    if (i < LDIM * MDIM * MDIM) g_kvs[i] = 0.f;
    if (i < LDIM * MDIM) { g_ks_sum[i] = 0.f; g_vs_sum[i] = 0.f; }
    if (i < 4) g_scal[i] = 0.f;
}

// ---------------- kernel 1: projections + reductions ----------------
// 128 threads = 4 warps; thread tid owns row b0+tid; each thread computes ALL 20 m
// (x read from smem once per element). d streamed in 4 chunks of 64.
extern __shared__ float smem1[];

__global__ __launch_bounds__(128) void k_pass1(const float* __restrict__ key,
                                               const float* __restrict__ query,
                                               const float* __restrict__ value,
                                               const float* __restrict__ bk,
                                               const float* __restrict__ bq,
                                               const float* __restrict__ bv) {
    float* x_s = smem1;                        // [128][68]
    float* w_s = x_s + RT * XST;               // [20][68]
    float* kt  = w_s + MDIM * XST;             // [128][20]
    float* vt  = kt + RT * MDIM;               // [128][20]
    float* kvp = vt + RT * MDIM;               // [4][20][20]
    float* red = kvp + 4 * MDIM * MDIM;        // [4][4]

    const int tid = threadIdx.x;
    const int w = tid >> 5, lane = tid & 31;
    const int l = blockIdx.y;
    const int b0 = blockIdx.x * RT;

    float stats[4] = {0.f, 0.f, 0.f, 0.f};     // sk, ssk, sq, ssq

    #pragma unroll 1
    for (int p = 0; p < 3; p++) {
        const float* src  = (p == 0) ? key : ((p == 1) ? query : value);
        const float* bias = (p == 0) ? bk  : ((p == 1) ? bq    : bv);

        u64 acc[MDIM];
        #pragma unroll
        for (int m = 0; m < MDIM; m++) acc[m] = 0ull;

        #pragma unroll 1
        for (int c = 0; c < NCH; c++) {
            __syncthreads();   // x_s/w_s free from previous chunk's consumers
            // stage x chunk: 128 rows x 64 d = 2048 float4 (16 per thread)
            #pragma unroll
            for (int i = 0; i < 16; i++) {
                int idx = i * 128 + tid;
                int r = idx >> 4, q4 = idx & 15;
                float4 v4 = *reinterpret_cast<const float4*>(
                    src + ((size_t)(b0 + r) * LDIM + l) * DDIM + c * CHUNK + q4 * 4);
                *reinterpret_cast<float4*>(x_s + r * XST + q4 * 4) = v4;
            }
            // stage w chunk: 20 x 64 = 320 float4
            #pragma unroll
            for (int i = 0; i < 3; i++) {
                int idx = i * 128 + tid;
                if (idx < MDIM * 16) {
                    int m = idx >> 4, q4 = idx & 15;
                    float4 v4 = *reinterpret_cast<const float4*>(
                        g_Wt + p * MDIM * DDIM + m * DDIM + c * CHUNK + q4 * 4);
                    *reinterpret_cast<float4*>(w_s + m * XST + q4 * 4) = v4;
                }
            }
            __syncthreads();

            const float* xr = x_s + tid * XST;
            #pragma unroll 4
            for (int d4 = 0; d4 < 16; d4++) {
                ulonglong2 xv = *reinterpret_cast<const ulonglong2*>(xr + d4 * 4);
                #pragma unroll
                for (int m = 0; m < MDIM; m++) {
                    ulonglong2 wv = *reinterpret_cast<const ulonglong2*>(w_s + m * XST + d4 * 4);
                    acc[m] = ffma2(xv.x, wv.x, acc[m]);
                    acc[m] = ffma2(xv.y, wv.y, acc[m]);
                }
            }
        }

        // finalize projection for this thread's row
        float res[MDIM];
        #pragma unroll
        for (int m = 0; m < MDIM; m++) {
            float2 f = unpack2(acc[m]);
            res[m] = f.x + f.y + __ldg(bias + m);
        }
        if (p == 0) {
            #pragma unroll
            for (int m = 0; m < MDIM; m++) {
                kt[tid * MDIM + m] = res[m];
                stats[0] += res[m]; stats[1] += res[m] * res[m];
            }
        } else if (p == 1) {
            #pragma unroll
            for (int m = 0; m < MDIM; m++) { stats[2] += res[m]; stats[3] += res[m] * res[m]; }
            float* dst = g_qs + ((size_t)l * BATCH + b0 + tid) * MDIM;
            #pragma unroll
            for (int m = 0; m < MDIM; m += 4)
                *reinterpret_cast<float4*>(dst + m) =
                    make_float4(res[m], res[m + 1], res[m + 2], res[m + 3]);
        } else {
            #pragma unroll
            for (int m = 0; m < MDIM; m++) vt[tid * MDIM + m] = res[m];
        }
    }
    __syncthreads();

    // kvs partials (f32x2 over j-pairs): warp w reduces rows 32w..32w+31, lanes<20 own m
    if (lane < MDIM) {
        u64 a[MDIM / 2];
        #pragma unroll
        for (int j = 0; j < MDIM / 2; j++) a[j] = 0ull;
        #pragma unroll 4
        for (int rr = 0; rr < 32; rr++) {
            int r = w * 32 + rr;
            float km = kt[r * MDIM + lane];
            u64 kk = pack2(km, km);
            const u64* vrow = reinterpret_cast<const u64*>(vt + r * MDIM);
            #pragma unroll
            for (int j = 0; j < MDIM / 2; j++) a[j] = ffma2(kk, vrow[j], a[j]);
        }
        float2* dst = reinterpret_cast<float2*>(kvp + (w * MDIM + lane) * MDIM);
        #pragma unroll
        for (int j = 0; j < MDIM / 2; j++) dst[j] = unpack2(a[j]);
    }

    // scalar stats reduce
    #pragma unroll
    for (int off = 16; off; off >>= 1) {
        stats[0] += __shfl_down_sync(0xffffffffu, stats[0], off);
        stats[1] += __shfl_down_sync(0xffffffffu, stats[1], off);
        stats[2] += __shfl_down_sync(0xffffffffu, stats[2], off);
        stats[3] += __shfl_down_sync(0xffffffffu, stats[3], off);
    }
    if (lane == 0) {
        red[w * 4 + 0] = stats[0]; red[w * 4 + 1] = stats[1];
        red[w * 4 + 2] = stats[2]; red[w * 4 + 3] = stats[3];
    }
    __syncthreads();

    if (tid < 4) {
        float s = 0.f;
        #pragma unroll
        for (int ww = 0; ww < 4; ww++) s += red[ww * 4 + tid];
        // tid: 0=sk->scal[2], 1=ssk->scal[3], 2=sq->scal[0], 3=ssq->scal[1]
        atomicAdd(&g_scal[(tid + 2) & 3], s);
    }
    for (int i = tid; i < MDIM * MDIM; i += 128) {
        float s = 0.f;
        #pragma unroll
        for (int ww = 0; ww < 4; ww++) s += kvp[ww * MDIM * MDIM + i];
        atomicAdd(&g_kvs[l * MDIM * MDIM + i], s);
    }
    if (tid < MDIM) {
        float s1 = 0.f, s2 = 0.f;
        #pragma unroll 8
        for (int r = 0; r < RT; r++) { s1 += kt[r * MDIM + tid]; s2 += vt[r * MDIM + tid]; }
        atomicAdd(&g_ks_sum[l * MDIM + tid], s1);
        atomicAdd(&g_vs_sum[l * MDIM + tid], s2);
    }
}

// ---------------- kernel 2: P[l] = kvs[l] @ Wp, C[l] = vs_sum[l] @ Wp ----------------
__global__ __launch_bounds__(256) void k_mid(const float* __restrict__ Wp) {
    __shared__ float kvs_s[MDIM * MDIM];
    __shared__ float vsum_s[MDIM];
    int l = blockIdx.x, tid = threadIdx.x;
    for (int i = tid; i < MDIM * MDIM; i += 256) kvs_s[i] = g_kvs[l * MDIM * MDIM + i];
    if (tid < MDIM) vsum_s[tid] = g_vs_sum[l * MDIM + tid];
    __syncthreads();
    int d = tid;
    float wp[MDIM];
    #pragma unroll
    for (int m2 = 0; m2 < MDIM; m2++) wp[m2] = __ldg(Wp + m2 * DDIM + d);
    float c = 0.f;
    #pragma unroll
    for (int m2 = 0; m2 < MDIM; m2++) c += vsum_s[m2] * wp[m2];
    g_C[l * DDIM + d] = c;
    #pragma unroll 4
    for (int m = 0; m < MDIM; m++) {
        float s = 0.f;
        #pragma unroll
        for (int m2 = 0; m2 < MDIM; m2++) s += kvs_s[m * MDIM + m2] * wp[m2];
        g_P[((size_t)l * MDIM + m) * DDIM + d] = s;
    }
}

// ---------------- kernel 3: output ----------------
__global__ __launch_bounds__(256) void k_pass2(float* __restrict__ out,
                                               const float* __restrict__ bp) {
    __shared__ __align__(16) float P_s[MDIM * DDIM];
    __shared__ __align__(16) float C_s[DDIM];
    __shared__ __align__(16) float bp_s[DDIM];
    __shared__ float ksum_s[MDIM];
    __shared__ float qs_s[R2 * MDIM];
    const int tid = threadIdx.x, w = tid >> 5, lane = tid & 31;
    const int l = blockIdx.y, b0 = blockIdx.x * R2;

    for (int i = tid; i < MDIM * DDIM; i += 256) P_s[i] = g_P[(size_t)l * MDIM * DDIM + i];
    if (tid < DDIM) { C_s[tid] = g_C[l * DDIM + tid]; bp_s[tid] = bp[tid]; }
    if (tid < MDIM) ksum_s[tid] = g_ks_sum[l * MDIM + tid];
    for (int i = tid; i < R2 * MDIM; i += 256)
        qs_s[i] = g_qs[((size_t)l * BATCH + b0) * MDIM + i];

    float sq = g_scal[0], ssq = g_scal[1], sk = g_scal[2], ssk = g_scal[3];
    float alpha = (sq != 0.f && sk != 0.f) ? rsqrtf(ssq) * rsqrtf(ssk) : 1.f;
    __syncthreads();

    const int r0 = w * 4;
    const int dbase = lane * 4;
    u64 acc[4][4];           // [row][d-pair]: pairs (d,d+1),(d+2,d+3) at dbase and dbase+128
    #pragma unroll
    for (int rr = 0; rr < 4; rr++)
        #pragma unroll
        for (int j = 0; j < 4; j++) acc[rr][j] = 0ull;
    float s0 = 0.f, s1 = 0.f, s2 = 0.f, s3 = 0.f;

    #pragma unroll
    for (int m = 0; m < MDIM; m++) {
        float q0 = qs_s[(r0 + 0) * MDIM + m];
        float q1 = qs_s[(r0 + 1) * MDIM + m];
        float q2 = qs_s[(r0 + 2) * MDIM + m];
        float q3 = qs_s[(r0 + 3) * MDIM + m];
        float km = ksum_s[m];
        s0 += q0 * km; s1 += q1 * km; s2 += q2 * km; s3 += q3 * km;
        u64 qq0 = pack2(q0, q0), qq1 = pack2(q1, q1);
        u64 qq2 = pack2(q2, q2), qq3 = pack2(q3, q3);
        ulonglong2 p0 = *reinterpret_cast<const ulonglong2*>(&P_s[m * DDIM + dbase]);
        ulonglong2 p1 = *reinterpret_cast<const ulonglong2*>(&P_s[m * DDIM + dbase + 128]);
        acc[0][0] = ffma2(qq0, p0.x, acc[0][0]); acc[0][1] = ffma2(qq0, p0.y, acc[0][1]);
        acc[0][2] = ffma2(qq0, p1.x, acc[0][2]); acc[0][3] = ffma2(qq0, p1.y, acc[0][3]);
        acc[1][0] = ffma2(qq1, p0.x, acc[1][0]); acc[1][1] = ffma2(qq1, p0.y, acc[1][1]);
        acc[1][2] = ffma2(qq1, p1.x, acc[1][2]); acc[1][3] = ffma2(qq1, p1.y, acc[1][3]);
        acc[2][0] = ffma2(qq2, p0.x, acc[2][0]); acc[2][1] = ffma2(qq2, p0.y, acc[2][1]);
        acc[2][2] = ffma2(qq2, p1.x, acc[2][2]); acc[2][3] = ffma2(qq2, p1.y, acc[2][3]);
        acc[3][0] = ffma2(qq3, p0.x, acc[3][0]); acc[3][1] = ffma2(qq3, p0.y, acc[3][1]);
        acc[3][2] = ffma2(qq3, p1.x, acc[3][2]); acc[3][3] = ffma2(qq3, p1.y, acc[3][3]);
    }

    float sv[4] = {s0, s1, s2, s3};
    #pragma unroll
    for (int rr = 0; rr < 4; rr++) {
        float inv = 1.f / (alpha * sv[rr] + (float)BATCH);
        float ai = alpha * inv;
        size_t base = ((size_t)(b0 + r0 + rr) * LDIM + l) * DDIM;
        #pragma unroll
        for (int j = 0; j < 2; j++) {
            int d = dbase + j * 128;
            float2 a0 = unpack2(acc[rr][j * 2 + 0]);
            float2 a1 = unpack2(acc[rr][j * 2 + 1]);
            float4 c4 = *reinterpret_cast<const float4*>(&C_s[d]);
            float4 b4 = *reinterpret_cast<const float4*>(&bp_s[d]);
            float4 o;
            o.x = a0.x * ai + c4.x * inv + b4.x;
            o.y = a0.y * ai + c4.y * inv + b4.y;
            o.z = a1.x * ai + c4.z * inv + b4.z;
            o.w = a1.y * ai + c4.w * inv + b4.w;
            *reinterpret_cast<float4*>(out + base + d) = o;
        }
    }
}

// ---------------- launch ----------------
extern "C" void kernel_launch(void* const* d_in, const int* in_sizes, int n_in,
                              void* d_out, int out_size) {
    const float* key   = (const float*)d_in[0];
    const float* value = (const float*)d_in[1];
    const float* query = (const float*)d_in[2];
    const float* Wk = (const float*)d_in[3];
    const float* bk = (const float*)d_in[4];
    const float* Wq = (const float*)d_in[5];
    const float* bq = (const float*)d_in[6];
    const float* Wv = (const float*)d_in[7];
    const float* bv = (const float*)d_in[8];
    const float* Wp = (const float*)d_in[9];
    const float* bp = (const float*)d_in[10];
    float* out = (float*)d_out;
    (void)in_sizes; (void)n_in; (void)out_size;

    const int smem1_bytes = (RT * XST + MDIM * XST + 2 * RT * MDIM +
                             4 * MDIM * MDIM + 16) * (int)sizeof(float); // 67,264 B
    cudaFuncSetAttribute(k_pass1, cudaFuncAttributeMaxDynamicSharedMemorySize, smem1_bytes);

    k_init<<<104, 256>>>(Wk, Wq, Wv);
    k_pass1<<<dim3(BATCH / RT, LDIM), 128, smem1_bytes>>>(key, query, value, bk, bq, bv);
    k_mid<<<LDIM, 256>>>(Wp);
    k_pass2<<<dim3(BATCH / R2, LDIM), 256>>>(out, bp);
}

// round 5
// speedup vs baseline: 1.8673x; 1.8673x over previous
#include <cuda_runtime.h>
#include <cstddef>
#include <cstdint>

#define BATCH 4096
#define LDIM 64
#define DDIM 256
#define MDIM 20
#define RT 128       // rows per pass1 block
#define CHUNK 64     // d per chunk
#define XST 68       // padded row stride (floats), conflict-free for LDS.128
#define BR 128       // b rows per pass2 block
#define TB 64        // b tile in pass2

typedef unsigned long long u64;

// ---------------- f32x2 helpers ----------------
__device__ __forceinline__ u64 ffma2(u64 a, u64 b, u64 c) {
    u64 d;
    asm("fma.rn.f32x2 %0, %1, %2, %3;" : "=l"(d) : "l"(a), "l"(b), "l"(c));
    return d;
}
__device__ __forceinline__ u64 pack2(float x, float y) {
    u64 r;
    asm("mov.b64 %0, {%1, %2};" : "=l"(r) : "f"(x), "f"(y));
    return r;
}
__device__ __forceinline__ float2 unpack2(u64 a) {
    float2 f;
    asm("mov.b64 {%0, %1}, %2;" : "=f"(f.x), "=f"(f.y) : "l"(a));
    return f;
}
__device__ __forceinline__ void cp16(uint32_t smem_dst, const void* gsrc) {
    asm volatile("cp.async.cg.shared.global [%0], [%1], 16;" :: "r"(smem_dst), "l"(gsrc));
}

// ---------------- scratch ----------------
__device__ float g_Wt[3 * MDIM * DDIM];             // transposed weights [proj][m][d]
__device__ float g_qs[(size_t)LDIM * BATCH * MDIM]; // [l][b][m]
__device__ float g_kvs[LDIM * MDIM * MDIM];
__device__ float g_ks_sum[LDIM * MDIM];
__device__ float g_vs_sum[LDIM * MDIM];
__device__ float g_scal[4];                         // sum_q, ssq_q, sum_k, ssq_k
__device__ float g_P[(size_t)LDIM * MDIM * DDIM];   // kvs @ Wp
__device__ float g_C[LDIM * DDIM];                  // vs_sum @ Wp

// ---------------- kernel 0 ----------------
__global__ __launch_bounds__(256) void k_init(const float* __restrict__ Wk,
                                              const float* __restrict__ Wq,
                                              const float* __restrict__ Wv) {
    int i = blockIdx.x * 256 + threadIdx.x;
    if (i < 3 * MDIM * DDIM) {
        int p = i / (MDIM * DDIM);
        int rem = i % (MDIM * DDIM);
        int m = rem / DDIM, d = rem % DDIM;
        const float* W = (p == 0) ? Wk : ((p == 1) ? Wq : Wv);
        g_Wt[i] = W[d * MDIM + m];
    }
    if (i < LDIM * MDIM * MDIM) g_kvs[i] = 0.f;
    if (i < LDIM * MDIM) { g_ks_sum[i] = 0.f; g_vs_sum[i] = 0.f; }
    if (i < 4) g_scal[i] = 0.f;
}

// ---------------- kernel 1: projections + reductions ----------------
// 256 threads. row = tid&127, mh = tid>>7 (each thread: 10 m for its row).
// cp.async double-buffered chunks: 12 (p,c) stages, pipeline depth 1.
extern __shared__ float smem1[];

// smem float offsets
#define O_X0 0
#define O_X1 (RT * XST)                 // 8704
#define O_W0 (2 * RT * XST)             // 17408
#define O_W1 (O_W0 + MDIM * XST)        // 18768
#define O_KT (O_W1 + MDIM * XST)        // 20128
#define O_VT (O_KT + RT * MDIM)         // 22688
#define O_RED (O_VT + RT * MDIM)        // 25248
#define SM1_FLOATS (O_RED + 32)         // 25280

__global__ __launch_bounds__(256) void k_pass1(const float* __restrict__ key,
                                               const float* __restrict__ query,
                                               const float* __restrict__ value,
                                               const float* __restrict__ bk,
                                               const float* __restrict__ bq,
                                               const float* __restrict__ bv) {
    const int tid = threadIdx.x;
    const int row = tid & 127, mh = tid >> 7;
    const int w = tid >> 5, lane = tid & 31;
    const int l = blockIdx.y;
    const int b0 = blockIdx.x * RT;

    float* kt = smem1 + O_KT;
    float* vt = smem1 + O_VT;
    float* red = smem1 + O_RED;
    const uint32_t sbase = (uint32_t)__cvta_generic_to_shared(smem1);

    const float* srcs[3] = {key, query, value};
    const float* biases[3] = {bk, bq, bv};

    // ---- stage helper ----
#define STAGE(J) do {                                                        \
        int sp = (J) >> 2, sc_ = (J) & 3, bf = (J) & 1;                      \
        const float* src = srcs[sp];                                         \
        uint32_t xd = sbase + (bf ? O_X1 : O_X0) * 4;                        \
        _Pragma("unroll")                                                    \
        for (int i_ = 0; i_ < 8; i_++) {                                     \
            int idx = i_ * 256 + tid;                                        \
            int r_ = idx >> 4, q4 = idx & 15;                                \
            const float* g = src + ((size_t)(b0 + r_) * LDIM + l) * DDIM +   \
                             sc_ * CHUNK + q4 * 4;                           \
            cp16(xd + (uint32_t)(r_ * XST + q4 * 4) * 4, g);                 \
        }                                                                    \
        uint32_t wd = sbase + (bf ? O_W1 : O_W0) * 4;                        \
        {                                                                    \
            int idx = tid;                                                   \
            int m_ = idx >> 4, q4 = idx & 15;                                \
            if (idx < MDIM * 16)                                             \
                cp16(wd + (uint32_t)(m_ * XST + q4 * 4) * 4,                 \
                     g_Wt + sp * MDIM * DDIM + m_ * DDIM + sc_ * CHUNK + q4 * 4); \
            idx = 256 + tid;                                                 \
            m_ = idx >> 4; q4 = idx & 15;                                    \
            if (idx < MDIM * 16)                                             \
                cp16(wd + (uint32_t)(m_ * XST + q4 * 4) * 4,                 \
                     g_Wt + sp * MDIM * DDIM + m_ * DDIM + sc_ * CHUNK + q4 * 4); \
        }                                                                    \
        asm volatile("cp.async.commit_group;");                              \
    } while (0)

    float sk = 0.f, ssk = 0.f, sq = 0.f, ssq = 0.f;
    u64 acc[10];

    STAGE(0);

    #pragma unroll 1
    for (int idx = 0; idx < 12; idx++) {
        const int p = idx >> 2, c = idx & 3, bf = idx & 1;
        if (c == 0) {
            #pragma unroll
            for (int j = 0; j < 10; j++) acc[j] = 0ull;
        }
        if (idx < 11) {
            STAGE(idx + 1);
            asm volatile("cp.async.wait_group 1;");
        } else {
            asm volatile("cp.async.wait_group 0;");
        }
        __syncthreads();

        const float* xr = smem1 + (bf ? O_X1 : O_X0) + row * XST;
        const float* wb = smem1 + (bf ? O_W1 : O_W0) + mh * 10 * XST;
        #pragma unroll 4
        for (int d4 = 0; d4 < 16; d4++) {
            ulonglong2 xv = *reinterpret_cast<const ulonglong2*>(xr + d4 * 4);
            #pragma unroll
            for (int j = 0; j < 10; j++) {
                ulonglong2 wv = *reinterpret_cast<const ulonglong2*>(wb + j * XST + d4 * 4);
                acc[j] = ffma2(xv.x, wv.x, acc[j]);
                acc[j] = ffma2(xv.y, wv.y, acc[j]);
            }
        }

        if (c == 3) {
            const float* bias = biases[p];
            float res[10];
            #pragma unroll
            for (int j = 0; j < 10; j++) {
                float2 f = unpack2(acc[j]);
                res[j] = f.x + f.y + __ldg(bias + mh * 10 + j);
            }
            if (p == 0) {
                #pragma unroll
                for (int j = 0; j < 10; j++) {
                    kt[row * MDIM + mh * 10 + j] = res[j];
                    sk += res[j]; ssk += res[j] * res[j];
                }
            } else if (p == 1) {
                #pragma unroll
                for (int j = 0; j < 10; j++) { sq += res[j]; ssq += res[j] * res[j]; }
                float* dst = g_qs + ((size_t)l * BATCH + b0 + row) * MDIM + mh * 10;
                #pragma unroll
                for (int j = 0; j < 10; j += 2)
                    *reinterpret_cast<float2*>(dst + j) = make_float2(res[j], res[j + 1]);
            } else {
                #pragma unroll
                for (int j = 0; j < 10; j++) vt[row * MDIM + mh * 10 + j] = res[j];
            }
        }
        __syncthreads();
    }
#undef STAGE

    // ---- kvs partials: warp w reduces rows 16w..16w+15; lanes<20 own m ----
    float* kvp = smem1 + O_X0;   // alias x0 (free now): [8][20][20] = 3200 floats
    if (lane < MDIM) {
        u64 a[10];
        #pragma unroll
        for (int j = 0; j < 10; j++) a[j] = 0ull;
        #pragma unroll 4
        for (int rr = 0; rr < 16; rr++) {
            int r = w * 16 + rr;
            float km = kt[r * MDIM + lane];
            u64 kk = pack2(km, km);
            const u64* vrow = reinterpret_cast<const u64*>(vt + r * MDIM);
            #pragma unroll
            for (int j = 0; j < 10; j++) a[j] = ffma2(kk, vrow[j], a[j]);
        }
        float2* dst = reinterpret_cast<float2*>(kvp + (w * MDIM + lane) * MDIM);
        #pragma unroll
        for (int j = 0; j < 10; j++) dst[j] = unpack2(a[j]);
    }

    // ---- scalar stats ----
    #pragma unroll
    for (int off = 16; off; off >>= 1) {
        sk  += __shfl_down_sync(0xffffffffu, sk,  off);
        ssk += __shfl_down_sync(0xffffffffu, ssk, off);
        sq  += __shfl_down_sync(0xffffffffu, sq,  off);
        ssq += __shfl_down_sync(0xffffffffu, ssq, off);
    }
    if (lane == 0) { red[w*4+0] = sk; red[w*4+1] = ssk; red[w*4+2] = sq; red[w*4+3] = ssq; }
    __syncthreads();

    if (tid < 4) {
        float s = 0.f;
        #pragma unroll
        for (int ww = 0; ww < 8; ww++) s += red[ww * 4 + tid];
        // tid: 0=sk->scal[2], 1=ssk->scal[3], 2=sq->scal[0], 3=ssq->scal[1]
        atomicAdd(&g_scal[(tid + 2) & 3], s);
    }
    for (int i = tid; i < MDIM * MDIM; i += 256) {
        float s = 0.f;
        #pragma unroll
        for (int ww = 0; ww < 8; ww++) s += kvp[ww * MDIM * MDIM + i];
        atomicAdd(&g_kvs[l * MDIM * MDIM + i], s);
    }
    if (tid < MDIM) {
        float s1 = 0.f, s2 = 0.f;
        #pragma unroll 8
        for (int r = 0; r < RT; r++) { s1 += kt[r * MDIM + tid]; s2 += vt[r * MDIM + tid]; }
        atomicAdd(&g_ks_sum[l * MDIM + tid], s1);
        atomicAdd(&g_vs_sum[l * MDIM + tid], s2);
    }
}

// ---------------- kernel 2: P[l] = kvs[l] @ Wp, C[l] = vs_sum[l] @ Wp ----------------
__global__ __launch_bounds__(256) void k_mid(const float* __restrict__ Wp) {
    __shared__ float kvs_s[MDIM * MDIM];
    __shared__ float vsum_s[MDIM];
    int l = blockIdx.x, tid = threadIdx.x;
    for (int i = tid; i < MDIM * MDIM; i += 256) kvs_s[i] = g_kvs[l * MDIM * MDIM + i];
    if (tid < MDIM) vsum_s[tid] = g_vs_sum[l * MDIM + tid];
    __syncthreads();
    int d = tid;
    float wp[MDIM];
    #pragma unroll
    for (int m2 = 0; m2 < MDIM; m2++) wp[m2] = __ldg(Wp + m2 * DDIM + d);
    float c = 0.f;
    #pragma unroll
    for (int m2 = 0; m2 < MDIM; m2++) c += vsum_s[m2] * wp[m2];
    g_C[l * DDIM + d] = c;
    #pragma unroll 4
    for (int m = 0; m < MDIM; m++) {
        float s = 0.f;
        #pragma unroll
        for (int m2 = 0; m2 < MDIM; m2++) s += kvs_s[m * MDIM + m2] * wp[m2];
        g_P[((size_t)l * MDIM + m) * DDIM + d] = s;
    }
}

// ---------------- kernel 3: output, P register-resident ----------------
// Block: 256 threads; thread owns d = tid. Block handles (l, 128 b-rows).
// out[b][l][d] = dot20(qs[b], P[:,d])*ai_b + C[d]*inv_b + bp[d]
__global__ __launch_bounds__(256) void k_pass2(float* __restrict__ out,
                                               const float* __restrict__ bp) {
    __shared__ __align__(16) float qtile[TB * MDIM];
    __shared__ float sc[TB * 2];       // per-b: ai, inv
    __shared__ float ksum_s[MDIM];
    const int tid = threadIdx.x;
    const int l = blockIdx.y, b0 = blockIdx.x * BR;

    // P column in registers as m-pairs
    u64 p2[10];
    #pragma unroll
    for (int j = 0; j < 10; j++) {
        float plo = g_P[((size_t)l * MDIM + 2 * j) * DDIM + tid];
        float phi = g_P[((size_t)l * MDIM + 2 * j + 1) * DDIM + tid];
        p2[j] = pack2(plo, phi);
    }
    float Cd = g_C[l * DDIM + tid];
    float bpd = __ldg(bp + tid);
    if (tid < MDIM) ksum_s[tid] = g_ks_sum[l * MDIM + tid];

    float sqs = g_scal[0], ssq = g_scal[1], sks = g_scal[2], ssk = g_scal[3];
    float alpha = (sqs != 0.f && sks != 0.f) ? rsqrtf(ssq) * rsqrtf(ssk) : 1.f;

    #pragma unroll 1
    for (int t = 0; t < BR / TB; t++) {
        __syncthreads();   // protect qtile/sc from previous tile's readers; orders ksum_s
        const size_t qbase = ((size_t)l * BATCH + b0 + t * TB) * MDIM;
        for (int i = tid; i < TB * MDIM / 4; i += 256)
            *reinterpret_cast<float4*>(qtile + i * 4) =
                *reinterpret_cast<const float4*>(g_qs + qbase + i * 4);
        if (tid < TB) {
            const float* qr = g_qs + qbase + (size_t)tid * MDIM;
            float s = 0.f;
            #pragma unroll
            for (int m = 0; m < MDIM; m++) s += __ldg(qr + m) * ksum_s[m];
            float inv = 1.f / (alpha * s + (float)BATCH);
            sc[tid * 2] = alpha * inv;
            sc[tid * 2 + 1] = inv;
        }
        __syncthreads();

        #pragma unroll 2
        for (int b = 0; b < TB; b += 2) {
            const u64* q0 = reinterpret_cast<const u64*>(qtile + b * MDIM);
            const u64* q1 = q0 + 10;
            u64 a0 = 0ull, a1 = 0ull;
            #pragma unroll
            for (int j = 0; j < 10; j++) {
                a0 = ffma2(q0[j], p2[j], a0);
                a1 = ffma2(q1[j], p2[j], a1);
            }
            float2 f0 = unpack2(a0), f1 = unpack2(a1);
            float dot0 = f0.x + f0.y, dot1 = f1.x + f1.y;
            float o0 = fmaf(dot0, sc[b * 2], fmaf(Cd, sc[b * 2 + 1], bpd));
            float o1 = fmaf(dot1, sc[b * 2 + 2], fmaf(Cd, sc[b * 2 + 3], bpd));
            size_t ob = ((size_t)(b0 + t * TB + b) * LDIM + l) * DDIM + tid;
            out[ob] = o0;
            out[ob + (size_t)LDIM * DDIM] = o1;
        }
    }
}

// ---------------- launch ----------------
extern "C" void kernel_launch(void* const* d_in, const int* in_sizes, int n_in,
                              void* d_out, int out_size) {
    const float* key   = (const float*)d_in[0];
    const float* value = (const float*)d_in[1];
    const float* query = (const float*)d_in[2];
    const float* Wk = (const float*)d_in[3];
    const float* bk = (const float*)d_in[4];
    const float* Wq = (const float*)d_in[5];
    const float* bq = (const float*)d_in[6];
    const float* Wv = (const float*)d_in[7];
    const float* bv = (const float*)d_in[8];
    const float* Wp = (const float*)d_in[9];
    const float* bp = (const float*)d_in[10];
    float* out = (float*)d_out;
    (void)in_sizes; (void)n_in; (void)out_size;

    const int smem1_bytes = SM1_FLOATS * (int)sizeof(float);  // 101,120 B
    cudaFuncSetAttribute(k_pass1, cudaFuncAttributeMaxDynamicSharedMemorySize, smem1_bytes);

    k_init<<<104, 256>>>(Wk, Wq, Wv);
    k_pass1<<<dim3(BATCH / RT, LDIM), 256, smem1_bytes>>>(key, query, value, bk, bq, bv);
    k_mid<<<LDIM, 256>>>(Wp);
    k_pass2<<<dim3(BATCH / BR, LDIM), 256>>>(out, bp);
}

// round 6
// speedup vs baseline: 2.2005x; 1.1784x over previous
#include <cuda_runtime.h>
#include <cstddef>
#include <cstdint>

#define BATCH 4096
#define LDIM 64
#define DDIM 256
#define MDIM 20
#define RT1 256      // rows per pass1 block (row-pairs per thread)
#define NST 48       // stages: 3 proj x 16 k-chunks of 16
#define XS 20        // padded stride for 16-float rows
#define BR2 128      // b rows per pass2 block
#define TB2 64       // b tile in pass2

typedef unsigned long long u64;

// ---------------- f32x2 helpers ----------------
__device__ __forceinline__ u64 ffma2(u64 a, u64 b, u64 c) {
    u64 d;
    asm("fma.rn.f32x2 %0, %1, %2, %3;" : "=l"(d) : "l"(a), "l"(b), "l"(c));
    return d;
}
__device__ __forceinline__ u64 pack2(float x, float y) {
    u64 r;
    asm("mov.b64 %0, {%1, %2};" : "=l"(r) : "f"(x), "f"(y));
    return r;
}
__device__ __forceinline__ float2 unpack2(u64 a) {
    float2 f;
    asm("mov.b64 {%0, %1}, %2;" : "=f"(f.x), "=f"(f.y) : "l"(a));
    return f;
}
__device__ __forceinline__ void cp16(uint32_t smem_dst, const void* gsrc) {
    asm volatile("cp.async.cg.shared.global [%0], [%1], 16;" :: "r"(smem_dst), "l"(gsrc));
}

// ---------------- scratch ----------------
__device__ float g_Wt[3 * MDIM * DDIM];             // transposed weights [proj][m][d]
__device__ float g_qs[(size_t)LDIM * BATCH * MDIM]; // [l][b][m]
__device__ float g_kvs[LDIM * MDIM * MDIM];
__device__ float g_ks_sum[LDIM * MDIM];
__device__ float g_vs_sum[LDIM * MDIM];
__device__ float g_scal[4];                         // sum_q, ssq_q, sum_k, ssq_k
__device__ float g_P[(size_t)LDIM * MDIM * DDIM];   // kvs @ Wp
__device__ float g_C[LDIM * DDIM];                  // vs_sum @ Wp

// ---------------- kernel 0 ----------------
__global__ __launch_bounds__(256) void k_init(const float* __restrict__ Wk,
                                              const float* __restrict__ Wq,
                                              const float* __restrict__ Wv) {
    int i = blockIdx.x * 256 + threadIdx.x;
    if (i < 3 * MDIM * DDIM) {
        int p = i / (MDIM * DDIM);
        int rem = i % (MDIM * DDIM);
        int m = rem / DDIM, d = rem % DDIM;
        const float* W = (p == 0) ? Wk : ((p == 1) ? Wq : Wv);
        g_Wt[i] = W[d * MDIM + m];
    }
    if (i < LDIM * MDIM * MDIM) g_kvs[i] = 0.f;
    if (i < LDIM * MDIM) { g_ks_sum[i] = 0.f; g_vs_sum[i] = 0.f; }
    if (i < 4) g_scal[i] = 0.f;
}

// ---------------- kernel 1: projections + reductions ----------------
// 256 threads; rp = tid&127 owns rows 2rp, 2rp+1 (even/odd split x arrays);
// mh = tid>>7 owns 10 m. 48 stages of 16 d, 3-buffer cp.async ring (depth 2).
extern __shared__ float smem1[];

// smem float offsets
#define O_XE 0                            // [3][128*20]
#define O_XO 7680                         // [3][128*20]
#define O_WB 15360                        // [3][20*20]
#define O_KT 16560                        // [256][20]
#define O_VT 21680                        // [256][20]
#define O_RED 26800                       // [8][4]
#define SM1_FLOATS 26832                  // 107,328 bytes

__global__ __launch_bounds__(256, 2) void k_pass1(const float* __restrict__ key,
                                                  const float* __restrict__ query,
                                                  const float* __restrict__ value,
                                                  const float* __restrict__ bk,
                                                  const float* __restrict__ bq,
                                                  const float* __restrict__ bv) {
    const int tid = threadIdx.x;
    const int rp = tid & 127, mh = tid >> 7;
    const int w = tid >> 5, lane = tid & 31;
    const int l = blockIdx.y;
    const int b0 = blockIdx.x * RT1;

    float* kt = smem1 + O_KT;
    float* vt = smem1 + O_VT;
    float* red = smem1 + O_RED;
    const uint32_t sbase = (uint32_t)__cvta_generic_to_shared(smem1);

    const float* srcs[3] = {key, query, value};
    const float* biases[3] = {bk, bq, bv};

#define STAGE(J) do {                                                         \
        int sp = (J) >> 4, kc = (J) & 15, bf = (J) % 3;                       \
        const float* src = srcs[sp];                                          \
        _Pragma("unroll")                                                     \
        for (int i_ = 0; i_ < 4; i_++) {                                      \
            int idx = i_ * 256 + tid;                                         \
            int r_ = idx >> 2, q_ = idx & 3;                                  \
            uint32_t xoff = ((r_ & 1) ? O_XO : O_XE) + bf * 2560 +            \
                            (r_ >> 1) * XS + q_ * 4;                          \
            const float* g = src + ((size_t)(b0 + r_) * LDIM + l) * DDIM +    \
                             kc * 16 + q_ * 4;                                \
            cp16(sbase + xoff * 4, g);                                        \
        }                                                                     \
        if (tid < 80) {                                                       \
            int m_ = tid >> 2, q_ = tid & 3;                                  \
            uint32_t woff = O_WB + bf * 400 + m_ * XS + q_ * 4;               \
            cp16(sbase + woff * 4,                                            \
                 g_Wt + sp * MDIM * DDIM + m_ * DDIM + kc * 16 + q_ * 4);     \
        }                                                                     \
        asm volatile("cp.async.commit_group;");                               \
    } while (0)

    float sk = 0.f, ssk = 0.f, sq = 0.f, ssq = 0.f;
    u64 ae[10], ao[10];

    STAGE(0);
    STAGE(1);

    #pragma unroll 1
    for (int s = 0; s < NST; s++) {
        const int bf = s % 3;
        if ((s & 15) == 0) {
            #pragma unroll
            for (int j = 0; j < 10; j++) { ae[j] = 0ull; ao[j] = 0ull; }
        }
        if (s < NST - 1) { asm volatile("cp.async.wait_group 1;"); }
        else             { asm volatile("cp.async.wait_group 0;"); }
        __syncthreads();
        if (s + 2 < NST) STAGE(s + 2);

        const float* xe = smem1 + O_XE + bf * 2560 + rp * XS;
        const float* xo = smem1 + O_XO + bf * 2560 + rp * XS;
        const float* wb = smem1 + O_WB + bf * 400 + mh * 10 * XS;
        #pragma unroll
        for (int q = 0; q < 4; q++) {
            ulonglong2 ue = *reinterpret_cast<const ulonglong2*>(xe + q * 4);
            ulonglong2 uo = *reinterpret_cast<const ulonglong2*>(xo + q * 4);
            #pragma unroll
            for (int j = 0; j < 10; j++) {
                ulonglong2 wq = *reinterpret_cast<const ulonglong2*>(wb + j * XS + q * 4);
                ae[j] = ffma2(ue.x, wq.x, ae[j]);
                ae[j] = ffma2(ue.y, wq.y, ae[j]);
                ao[j] = ffma2(uo.x, wq.x, ao[j]);
                ao[j] = ffma2(uo.y, wq.y, ao[j]);
            }
        }

        if ((s & 15) == 15) {
            const int p = s >> 4;
            const float* bias = biases[p];
            const int mb = mh * 10;
            float re[10], ro[10];
            #pragma unroll
            for (int j = 0; j < 10; j++) {
                float bj = __ldg(bias + mb + j);
                float2 fe = unpack2(ae[j]);
                float2 fo = unpack2(ao[j]);
                re[j] = fe.x + fe.y + bj;
                ro[j] = fo.x + fo.y + bj;
            }
            const int r0 = 2 * rp, r1 = 2 * rp + 1;
            if (p == 0) {
                #pragma unroll
                for (int j = 0; j < 10; j++) {
                    kt[r0 * MDIM + mb + j] = re[j];
                    kt[r1 * MDIM + mb + j] = ro[j];
                    sk += re[j] + ro[j];
                    ssk += re[j] * re[j] + ro[j] * ro[j];
                }
            } else if (p == 1) {
                #pragma unroll
                for (int j = 0; j < 10; j++) {
                    sq += re[j] + ro[j];
                    ssq += re[j] * re[j] + ro[j] * ro[j];
                }
                float* d0 = g_qs + ((size_t)l * BATCH + b0 + r0) * MDIM + mb;
                float* d1 = g_qs + ((size_t)l * BATCH + b0 + r1) * MDIM + mb;
                #pragma unroll
                for (int j = 0; j < 10; j += 2) {
                    *reinterpret_cast<float2*>(d0 + j) = make_float2(re[j], re[j + 1]);
                    *reinterpret_cast<float2*>(d1 + j) = make_float2(ro[j], ro[j + 1]);
                }
            } else {
                #pragma unroll
                for (int j = 0; j < 10; j++) {
                    vt[r0 * MDIM + mb + j] = re[j];
                    vt[r1 * MDIM + mb + j] = ro[j];
                }
            }
        }
    }
#undef STAGE
    __syncthreads();

    // ---- kvs partials: warp w reduces rows 32w..32w+31; lanes<20 own m ----
    float* kvp = smem1 + O_XE;   // alias x region: [8][20][20] = 3200 floats
    if (lane < MDIM) {
        u64 a[10];
        #pragma unroll
        for (int j = 0; j < 10; j++) a[j] = 0ull;
        #pragma unroll 4
        for (int rr = 0; rr < 32; rr++) {
            int r = w * 32 + rr;
            float km = kt[r * MDIM + lane];
            u64 kk = pack2(km, km);
            const u64* vrow = reinterpret_cast<const u64*>(vt + r * MDIM);
            #pragma unroll
            for (int j = 0; j < 10; j++) a[j] = ffma2(kk, vrow[j], a[j]);
        }
        float2* dst = reinterpret_cast<float2*>(kvp + (w * MDIM + lane) * MDIM);
        #pragma unroll
        for (int j = 0; j < 10; j++) dst[j] = unpack2(a[j]);
    }

    // ---- scalar stats ----
    #pragma unroll
    for (int off = 16; off; off >>= 1) {
        sk  += __shfl_down_sync(0xffffffffu, sk,  off);
        ssk += __shfl_down_sync(0xffffffffu, ssk, off);
        sq  += __shfl_down_sync(0xffffffffu, sq,  off);
        ssq += __shfl_down_sync(0xffffffffu, ssq, off);
    }
    if (lane == 0) { red[w*4+0] = sk; red[w*4+1] = ssk; red[w*4+2] = sq; red[w*4+3] = ssq; }
    __syncthreads();

    if (tid < 4) {
        float s = 0.f;
        #pragma unroll
        for (int ww = 0; ww < 8; ww++) s += red[ww * 4 + tid];
        // tid: 0=sk->scal[2], 1=ssk->scal[3], 2=sq->scal[0], 3=ssq->scal[1]
        atomicAdd(&g_scal[(tid + 2) & 3], s);
    }
    for (int i = tid; i < MDIM * MDIM; i += 256) {
        float s = 0.f;
        #pragma unroll
        for (int ww = 0; ww < 8; ww++) s += kvp[ww * MDIM * MDIM + i];
        atomicAdd(&g_kvs[l * MDIM * MDIM + i], s);
    }
    if (tid < MDIM) {
        float s1 = 0.f, s2 = 0.f;
        #pragma unroll 8
        for (int r = 0; r < RT1; r++) { s1 += kt[r * MDIM + tid]; s2 += vt[r * MDIM + tid]; }
        atomicAdd(&g_ks_sum[l * MDIM + tid], s1);
        atomicAdd(&g_vs_sum[l * MDIM + tid], s2);
    }
}

// ---------------- kernel 2: P[l] = kvs[l] @ Wp, C[l] = vs_sum[l] @ Wp ----------------
__global__ __launch_bounds__(256) void k_mid(const float* __restrict__ Wp) {
    __shared__ float kvs_s[MDIM * MDIM];
    __shared__ float vsum_s[MDIM];
    int l = blockIdx.x, tid = threadIdx.x;
    for (int i = tid; i < MDIM * MDIM; i += 256) kvs_s[i] = g_kvs[l * MDIM * MDIM + i];
    if (tid < MDIM) vsum_s[tid] = g_vs_sum[l * MDIM + tid];
    __syncthreads();
    int d = tid;
    float wp[MDIM];
    #pragma unroll
    for (int m2 = 0; m2 < MDIM; m2++) wp[m2] = __ldg(Wp + m2 * DDIM + d);
    float c = 0.f;
    #pragma unroll
    for (int m2 = 0; m2 < MDIM; m2++) c += vsum_s[m2] * wp[m2];
    g_C[l * DDIM + d] = c;
    #pragma unroll 4
    for (int m = 0; m < MDIM; m++) {
        float s = 0.f;
        #pragma unroll
        for (int m2 = 0; m2 < MDIM; m2++) s += kvs_s[m * MDIM + m2] * wp[m2];
        g_P[((size_t)l * MDIM + m) * DDIM + d] = s;
    }
}

// ---------------- kernel 3: output; thread owns a d-pair, P in regs ----------------
__global__ __launch_bounds__(256) void k_pass2(float* __restrict__ out,
                                               const float* __restrict__ bp) {
    __shared__ __align__(16) float qtile[TB2 * MDIM];
    __shared__ float2 sc2[TB2];        // per-b: (ai, inv)
    __shared__ float ksum_s[MDIM];
    const int tid = threadIdx.x;
    const int dp = tid & 127, g = tid >> 7;
    const int d0 = 2 * dp;
    const int l = blockIdx.y, b0 = blockIdx.x * BR2;

    // P columns d0, d0+1 in registers as m-pairs
    u64 pa[10], pb[10];
    #pragma unroll
    for (int j = 0; j < 10; j++) {
        const float* P0 = g_P + ((size_t)l * MDIM + 2 * j) * DDIM + d0;
        const float* P1 = g_P + ((size_t)l * MDIM + 2 * j + 1) * DDIM + d0;
        pa[j] = pack2(P0[0], P1[0]);
        pb[j] = pack2(P0[1], P1[1]);
    }
    float C0 = g_C[l * DDIM + d0], C1 = g_C[l * DDIM + d0 + 1];
    float bp0 = __ldg(bp + d0), bp1 = __ldg(bp + d0 + 1);
    if (tid < MDIM) ksum_s[tid] = g_ks_sum[l * MDIM + tid];

    float sqs = g_scal[0], ssq = g_scal[1], sks = g_scal[2], ssk = g_scal[3];
    float alpha = (sqs != 0.f && sks != 0.f) ? rsqrtf(ssq) * rsqrtf(ssk) : 1.f;

    #pragma unroll 1
    for (int t = 0; t < BR2 / TB2; t++) {
        __syncthreads();   // qtile/sc2 free from previous tile; orders ksum_s at t=0
        const size_t qbase = ((size_t)l * BATCH + b0 + t * TB2) * MDIM;
        for (int i = tid; i < TB2 * MDIM / 4; i += 256)
            *reinterpret_cast<float4*>(qtile + i * 4) =
                *reinterpret_cast<const float4*>(g_qs + qbase + i * 4);
        if (tid < TB2) {
            const float* qr = g_qs + qbase + (size_t)tid * MDIM;
            float s = 0.f;
            #pragma unroll
            for (int m = 0; m < MDIM; m++) s += __ldg(qr + m) * ksum_s[m];
            float inv = 1.f / (alpha * s + (float)BATCH);
            sc2[tid] = make_float2(alpha * inv, inv);
        }
        __syncthreads();

        // group g handles b rows [g*32, g*32+32) of the tile
        #pragma unroll 2
        for (int bb = 0; bb < TB2 / 2; bb++) {
            const int b = g * (TB2 / 2) + bb;
            const u64* q2 = reinterpret_cast<const u64*>(qtile + b * MDIM);
            u64 a0 = 0ull, a1 = 0ull;
            #pragma unroll
            for (int j = 0; j < 10; j++) {
                a0 = ffma2(q2[j], pa[j], a0);
                a1 = ffma2(q2[j], pb[j], a1);
            }
            float2 f0 = unpack2(a0), f1 = unpack2(a1);
            float2 s2 = sc2[b];
            float o0 = fmaf(f0.x + f0.y, s2.x, fmaf(C0, s2.y, bp0));
            float o1 = fmaf(f1.x + f1.y, s2.x, fmaf(C1, s2.y, bp1));
            size_t ob = ((size_t)(b0 + t * TB2 + b) * LDIM + l) * DDIM + d0;
            *reinterpret_cast<float2*>(out + ob) = make_float2(o0, o1);
        }
    }
}

// ---------------- launch ----------------
extern "C" void kernel_launch(void* const* d_in, const int* in_sizes, int n_in,
                              void* d_out, int out_size) {
    const float* key   = (const float*)d_in[0];
    const float* value = (const float*)d_in[1];
    const float* query = (const float*)d_in[2];
    const float* Wk = (const float*)d_in[3];
    const float* bk = (const float*)d_in[4];
    const float* Wq = (const float*)d_in[5];
    const float* bq = (const float*)d_in[6];
    const float* Wv = (const float*)d_in[7];
    const float* bv = (const float*)d_in[8];
    const float* Wp = (const float*)d_in[9];
    const float* bp = (const float*)d_in[10];
    float* out = (float*)d_out;
    (void)in_sizes; (void)n_in; (void)out_size;

    const int smem1_bytes = SM1_FLOATS * (int)sizeof(float);  // 107,328 B
    cudaFuncSetAttribute(k_pass1, cudaFuncAttributeMaxDynamicSharedMemorySize, smem1_bytes);

    k_init<<<104, 256>>>(Wk, Wq, Wv);
    k_pass1<<<dim3(BATCH / RT1, LDIM), 256, smem1_bytes>>>(key, query, value, bk, bq, bv);
    k_mid<<<LDIM, 256>>>(Wp);
    k_pass2<<<dim3(BATCH / BR2, LDIM), 256>>>(out, bp);
}

// round 8
// speedup vs baseline: 2.5235x; 1.1468x over previous
#include <cuda_runtime.h>
#include <cuda_bf16.h>
#include <cstddef>
#include <cstdint>

#define BATCH 4096
#define LDIM 64
#define DDIM 256
#define MDIM 20
#define BR2 128
#define TB2 64

typedef unsigned long long u64;

// ---------------- helpers ----------------
__device__ __forceinline__ u64 ffma2(u64 a, u64 b, u64 c) {
    u64 d;
    asm("fma.rn.f32x2 %0, %1, %2, %3;" : "=l"(d) : "l"(a), "l"(b), "l"(c));
    return d;
}
__device__ __forceinline__ u64 pack2(float x, float y) {
    u64 r;
    asm("mov.b64 %0, {%1, %2};" : "=l"(r) : "f"(x), "f"(y));
    return r;
}
__device__ __forceinline__ float2 unpack2(u64 a) {
    float2 f;
    asm("mov.b64 {%0, %1}, %2;" : "=f"(f.x), "=f"(f.y) : "l"(a));
    return f;
}
__device__ __forceinline__ void cp16(uint32_t smem_dst, const void* gsrc) {
    asm volatile("cp.async.cg.shared.global [%0], [%1], 16;" :: "r"(smem_dst), "l"(gsrc));
}
#define MMA_BF16(D, A0, A1, A2, A3, B0, B1)                                   \
    asm volatile(                                                             \
        "mma.sync.aligned.m16n8k16.row.col.f32.bf16.bf16.f32 "                \
        "{%0,%1,%2,%3}, {%4,%5,%6,%7}, {%8,%9}, {%0,%1,%2,%3};"               \
        : "+f"((D)[0]), "+f"((D)[1]), "+f"((D)[2]), "+f"((D)[3])              \
        : "r"(A0), "r"(A1), "r"(A2), "r"(A3), "r"(B0), "r"(B1))

// ---------------- scratch ----------------
// W packed for mma: [p][kc][split][24 n][64 k] bf16 (contiguous 128B rows)
__device__ __align__(16) __nv_bfloat16 g_Wb2[3 * 4 * 2 * 24 * 64];
__device__ float g_qs[(size_t)LDIM * BATCH * MDIM]; // [l][b][m]
__device__ float g_kvs[LDIM * MDIM * MDIM];
__device__ float g_ks_sum[LDIM * MDIM];
__device__ float g_vs_sum[LDIM * MDIM];
__device__ float g_scal[4];                         // sum_q, ssq_q, sum_k, ssq_k
__device__ float g_P[(size_t)LDIM * MDIM * DDIM];
__device__ float g_C[LDIM * DDIM];

// ---------------- kernel 0: weight split/pack + zero reductions ----------------
// grid 144 x 256 = 36,864 threads = one packed weight element each
__global__ __launch_bounds__(256) void k_init(const float* __restrict__ Wk,
                                              const float* __restrict__ Wq,
                                              const float* __restrict__ Wv) {
    int i = blockIdx.x * 256 + threadIdx.x;
    {
        int k = i & 63;
        int t = i >> 6;
        int n = t % 24; t /= 24;
        int s = t & 1; t >>= 1;
        int kc = t & 3, p = t >> 2;
        const float* W = (p == 0) ? Wk : ((p == 1) ? Wq : Wv);
        float wv = (n < MDIM) ? W[(kc * 64 + k) * MDIM + n] : 0.f;
        __nv_bfloat16 hi = __float2bfloat16(wv);
        __nv_bfloat16 val = s ? __float2bfloat16(wv - __bfloat162float(hi)) : hi;
        g_Wb2[i] = val;
    }
    if (i < LDIM * MDIM * MDIM) g_kvs[i] = 0.f;
    if (i < LDIM * MDIM) { g_ks_sum[i] = 0.f; g_vs_sum[i] = 0.f; }
    if (i < 4) g_scal[i] = 0.f;
}

// ---------------- kernel 1: mma.sync projections + reductions ----------------
// 256 thr (8 warps); block = (128 b-rows, one l). 12 stages (3 proj x 4 k64-chunks).
// x split to bf16 hi/lo in smem (row stride 72 bf16 -> conflict-free frag LDS);
// W hi/lo cp.async double-buffered. Warp w owns rows 16w..16w+15, 3 n-tiles of 8.
extern __shared__ float smem1[];

// byte offsets; x row stride = 72 bf16 = 144 B = 36 words
#define O_XH0 0
#define O_XL0 18432
#define O_XH1 36864
#define O_XL1 55296
#define O_WB0 73728             // per buf: 2 splits x 24 x 72 bf16 = 6912 B
#define O_WB1 80640
#define O_KT  87552             // float[128*20]
#define O_VT  97792
#define O_RED 108032            // float[32]
#define SM1_BYTES 108160

__global__ __launch_bounds__(256, 2) void k_pass1(const float* __restrict__ key,
                                                  const float* __restrict__ query,
                                                  const float* __restrict__ value,
                                                  const float* __restrict__ bk,
                                                  const float* __restrict__ bq,
                                                  const float* __restrict__ bv) {
    char* smem = reinterpret_cast<char*>(smem1);
    const int tid = threadIdx.x;
    const int w = tid >> 5, lane = tid & 31;
    const int qr = lane >> 2, qc = lane & 3;
    const int l = blockIdx.y;
    const int b0 = blockIdx.x * 128;
    uint32_t sb;
    asm("{ .reg .u64 t; cvta.to.shared.u64 t, %1; cvt.u32.u64 %0, t; }" : "=r"(sb) : "l"(smem));

    float* kt = reinterpret_cast<float*>(smem + O_KT);
    float* vt = reinterpret_cast<float*>(smem + O_VT);
    float* red = reinterpret_cast<float*>(smem + O_RED);

    const float* srcs[3] = {key, query, value};
    const float* biases[3] = {bk, bq, bv};

    const int rb = w * 16 + (lane >> 4);    // + 2*i -> 8 rows per thread
    const int cf = (lane & 15) * 4;         // float col within 64-chunk

#define LOAD_X(J) do {                                                        \
        int sp = (J) >> 2, skc = (J) & 3;                                     \
        const float* src = srcs[sp];                                          \
        _Pragma("unroll")                                                     \
        for (int i_ = 0; i_ < 8; i_++) {                                      \
            int r_ = rb + i_ * 2;                                             \
            xv[i_] = *reinterpret_cast<const float4*>(                        \
                src + ((size_t)(b0 + r_) * LDIM + l) * DDIM + skc * 64 + cf); \
        }                                                                     \
    } while (0)

#define STAGE_W(J, OFF) do {                                                  \
        int sp = (J) >> 2, skc = (J) & 3;                                     \
        if (tid < 192) {                                                      \
            _Pragma("unroll")                                                 \
            for (int jj_ = 0; jj_ < 2; jj_++) {                               \
                int idx = jj_ * 192 + tid;                                    \
                int ss = idx / 192;                                           \
                int rr_ = (idx % 192) >> 3;                                   \
                int qq = idx & 7;                                             \
                cp16(sb + (OFF) + (uint32_t)(ss * 3456 + rr_ * 144 + qq * 16),\
                     reinterpret_cast<const char*>(g_Wb2) +                   \
                     (((sp * 4 + skc) * 2 + ss) * 1536 + rr_ * 64) * 2 + qq * 16); \
            }                                                                 \
        }                                                                     \
        asm volatile("cp.async.commit_group;");                               \
    } while (0)

    float4 xv[8];
    STAGE_W(0, O_WB0);
    LOAD_X(0);

    float sk = 0.f, ssk = 0.f, sq = 0.f, ssq = 0.f;
    float acc[3][4];

    #pragma unroll 1
    for (int cs = 0; cs < 12; cs++) {
        const int p = cs >> 2, kc = cs & 3, buf = cs & 1;
        if (kc == 0) {
            #pragma unroll
            for (int nt = 0; nt < 3; nt++)
                #pragma unroll
                for (int j = 0; j < 4; j++) acc[nt][j] = 0.f;
        }

        // 1. convert + STS (hi/lo) into x buffer `buf`
        {
            const uint32_t xh_b = sb + (buf ? O_XH1 : O_XH0);
            const uint32_t xl_b = xh_b + 18432;
            #pragma unroll
            for (int i = 0; i < 8; i++) {
                int r = rb + i * 2;
                uint32_t off = (uint32_t)(r * 144 + (lane & 15) * 8);
                float v0 = xv[i].x, v1 = xv[i].y, v2 = xv[i].z, v3 = xv[i].w;
                __nv_bfloat162 h01 = __floats2bfloat162_rn(v0, v1);
                __nv_bfloat162 h23 = __floats2bfloat162_rn(v2, v3);
                uint32_t hw0 = *reinterpret_cast<uint32_t*>(&h01);
                uint32_t hw1 = *reinterpret_cast<uint32_t*>(&h23);
                __nv_bfloat162 l01 = __floats2bfloat162_rn(v0 - __bfloat162float(h01.x),
                                                           v1 - __bfloat162float(h01.y));
                __nv_bfloat162 l23 = __floats2bfloat162_rn(v2 - __bfloat162float(h23.x),
                                                           v3 - __bfloat162float(h23.y));
                uint32_t lw0 = *reinterpret_cast<uint32_t*>(&l01);
                uint32_t lw1 = *reinterpret_cast<uint32_t*>(&l23);
                asm volatile("st.shared.v2.b32 [%0], {%1, %2};"
                             :: "r"(xh_b + off), "r"(hw0), "r"(hw1));
                asm volatile("st.shared.v2.b32 [%0], {%1, %2};"
                             :: "r"(xl_b + off), "r"(lw0), "r"(lw1));
            }
        }
        // 2. prefetch next x chunk into regs (hidden behind compute)
        if (cs < 11) LOAD_X(cs + 1);
        // 3-4. W(cs) complete; staging visible; all warps done with compute(cs-1)
        asm volatile("cp.async.wait_group 0;");
        __syncthreads();
        // 5. launch W(cs+1) into the other W buffer
        if (cs < 11) STAGE_W(cs + 1, buf ? O_WB0 : O_WB1);

        // 6. compute: 4 k-steps x (3 n-tiles x 3 split-terms)
        {
            const uint32_t* xh = reinterpret_cast<const uint32_t*>(smem + (buf ? O_XH1 : O_XH0));
            const uint32_t* xl = xh + 4608;                 // 18432 B
            const uint32_t* wh = reinterpret_cast<const uint32_t*>(smem + (buf ? O_WB1 : O_WB0));
            const uint32_t* wl = wh + 864;                  // 3456 B
            const int WR = w * 16;
            #pragma unroll
            for (int ks = 0; ks < 4; ks++) {
                const int aw = (WR + qr) * 36 + ks * 8 + qc;
                uint32_t ah0 = xh[aw], ah1 = xh[aw + 288], ah2 = xh[aw + 4], ah3 = xh[aw + 292];
                uint32_t al0 = xl[aw], al1 = xl[aw + 288], al2 = xl[aw + 4], al3 = xl[aw + 292];
                #pragma unroll
                for (int nt = 0; nt < 3; nt++) {
                    const int bw = (nt * 8 + qr) * 36 + ks * 8 + qc;
                    uint32_t bh0 = wh[bw], bh1 = wh[bw + 4];
                    uint32_t bl0 = wl[bw], bl1 = wl[bw + 4];
                    MMA_BF16(acc[nt], ah0, ah1, ah2, ah3, bh0, bh1);
                    MMA_BF16(acc[nt], al0, al1, al2, al3, bh0, bh1);
                    MMA_BF16(acc[nt], ah0, ah1, ah2, ah3, bl0, bl1);
                }
            }
        }

        // 7. epilogue at proj end
        if (kc == 3) {
            const float* bias = biases[p];
            const int r0 = w * 16 + qr, r1 = r0 + 8;
            #pragma unroll
            for (int nt = 0; nt < 3; nt++) {
                const int c0 = nt * 8 + qc * 2;
                if (c0 < MDIM) {
                    float bb0 = __ldg(bias + c0), bb1 = __ldg(bias + c0 + 1);
                    float v00 = acc[nt][0] + bb0, v01 = acc[nt][1] + bb1;
                    float v10 = acc[nt][2] + bb0, v11 = acc[nt][3] + bb1;
                    if (p == 0) {
                        kt[r0 * MDIM + c0] = v00; kt[r0 * MDIM + c0 + 1] = v01;
                        kt[r1 * MDIM + c0] = v10; kt[r1 * MDIM + c0 + 1] = v11;
                        sk += v00 + v01 + v10 + v11;
                        ssk += v00 * v00 + v01 * v01 + v10 * v10 + v11 * v11;
                    } else if (p == 1) {
                        sq += v00 + v01 + v10 + v11;
                        ssq += v00 * v00 + v01 * v01 + v10 * v10 + v11 * v11;
                        *reinterpret_cast<float2*>(
                            g_qs + ((size_t)l * BATCH + b0 + r0) * MDIM + c0) = make_float2(v00, v01);
                        *reinterpret_cast<float2*>(
                            g_qs + ((size_t)l * BATCH + b0 + r1) * MDIM + c0) = make_float2(v10, v11);
                    } else {
                        vt[r0 * MDIM + c0] = v00; vt[r0 * MDIM + c0 + 1] = v01;
                        vt[r1 * MDIM + c0] = v10; vt[r1 * MDIM + c0 + 1] = v11;
                    }
                }
            }
        }
    }
#undef LOAD_X
#undef STAGE_W
    __syncthreads();

    // ---- kvs partials: warp w reduces rows 16w..16w+15; lanes<20 own m ----
    float* kvp = reinterpret_cast<float*>(smem);   // alias x region: [8][20][20]
    if (lane < MDIM) {
        u64 a[10];
        #pragma unroll
        for (int j = 0; j < 10; j++) a[j] = 0ull;
        #pragma unroll 4
        for (int rr = 0; rr < 16; rr++) {
            int r = w * 16 + rr;
            float km = kt[r * MDIM + lane];
            u64 kk = pack2(km, km);
            const u64* vrow = reinterpret_cast<const u64*>(vt + r * MDIM);
            #pragma unroll
            for (int j = 0; j < 10; j++) a[j] = ffma2(kk, vrow[j], a[j]);
        }
        float2* dst = reinterpret_cast<float2*>(kvp + (w * MDIM + lane) * MDIM);
        #pragma unroll
        for (int j = 0; j < 10; j++) dst[j] = unpack2(a[j]);
    }

    // ---- scalar stats ----
    #pragma unroll
    for (int off = 16; off; off >>= 1) {
        sk  += __shfl_down_sync(0xffffffffu, sk,  off);
        ssk += __shfl_down_sync(0xffffffffu, ssk, off);
        sq  += __shfl_down_sync(0xffffffffu, sq,  off);
        ssq += __shfl_down_sync(0xffffffffu, ssq, off);
    }
    if (lane == 0) { red[w*4+0] = sk; red[w*4+1] = ssk; red[w*4+2] = sq; red[w*4+3] = ssq; }
    __syncthreads();

    if (tid < 4) {
        float s = 0.f;
        #pragma unroll
        for (int ww = 0; ww < 8; ww++) s += red[ww * 4 + tid];
        atomicAdd(&g_scal[(tid + 2) & 3], s);   // 0=sk->2, 1=ssk->3, 2=sq->0, 3=ssq->1
    }
    for (int i = tid; i < MDIM * MDIM; i += 256) {
        float s = 0.f;
        #pragma unroll
        for (int ww = 0; ww < 8; ww++) s += kvp[ww * MDIM * MDIM + i];
        atomicAdd(&g_kvs[l * MDIM * MDIM + i], s);
    }
    if (tid < MDIM) {
        float s1 = 0.f, s2 = 0.f;
        #pragma unroll 8
        for (int r = 0; r < 128; r++) { s1 += kt[r * MDIM + tid]; s2 += vt[r * MDIM + tid]; }
        atomicAdd(&g_ks_sum[l * MDIM + tid], s1);
        atomicAdd(&g_vs_sum[l * MDIM + tid], s2);
    }
}

// ---------------- kernel 2: P[l] = kvs[l] @ Wp, C[l] = vs_sum[l] @ Wp ----------------
__global__ __launch_bounds__(256) void k_mid(const float* __restrict__ Wp) {
    __shared__ float kvs_s[MDIM * MDIM];
    __shared__ float vsum_s[MDIM];
    int l = blockIdx.x, tid = threadIdx.x;
    for (int i = tid; i < MDIM * MDIM; i += 256) kvs_s[i] = g_kvs[l * MDIM * MDIM + i];
    if (tid < MDIM) vsum_s[tid] = g_vs_sum[l * MDIM + tid];
    __syncthreads();
    int d = tid;
    float wp[MDIM];
    #pragma unroll
    for (int m2 = 0; m2 < MDIM; m2++) wp[m2] = __ldg(Wp + m2 * DDIM + d);
    float c = 0.f;
    #pragma unroll
    for (int m2 = 0; m2 < MDIM; m2++) c += vsum_s[m2] * wp[m2];
    g_C[l * DDIM + d] = c;
    #pragma unroll 4
    for (int m = 0; m < MDIM; m++) {
        float s = 0.f;
        #pragma unroll
        for (int m2 = 0; m2 < MDIM; m2++) s += kvs_s[m * MDIM + m2] * wp[m2];
        g_P[((size_t)l * MDIM + m) * DDIM + d] = s;
    }
}

// ---------------- kernel 3: output; thread owns a d-pair, P in regs ----------------
__global__ __launch_bounds__(256) void k_pass2(float* __restrict__ out,
                                               const float* __restrict__ bp) {
    __shared__ __align__(16) float qtile[TB2 * MDIM];
    __shared__ float2 sc2[TB2];
    __shared__ float ksum_s[MDIM];
    const int tid = threadIdx.x;
    const int dp = tid & 127, g = tid >> 7;
    const int d0 = 2 * dp;
    const int l = blockIdx.y, b0 = blockIdx.x * BR2;

    u64 pa[10], pb[10];
    #pragma unroll
    for (int j = 0; j < 10; j++) {
        const float* P0 = g_P + ((size_t)l * MDIM + 2 * j) * DDIM + d0;
        const float* P1 = g_P + ((size_t)l * MDIM + 2 * j + 1) * DDIM + d0;
        pa[j] = pack2(P0[0], P1[0]);
        pb[j] = pack2(P0[1], P1[1]);
    }
    float C0 = g_C[l * DDIM + d0], C1 = g_C[l * DDIM + d0 + 1];
    float bp0 = __ldg(bp + d0), bp1 = __ldg(bp + d0 + 1);
    if (tid < MDIM) ksum_s[tid] = g_ks_sum[l * MDIM + tid];

    float sqs = g_scal[0], ssq = g_scal[1], sks = g_scal[2], ssk = g_scal[3];
    float alpha = (sqs != 0.f && sks != 0.f) ? rsqrtf(ssq) * rsqrtf(ssk) : 1.f;

    #pragma unroll 1
    for (int t = 0; t < BR2 / TB2; t++) {
        __syncthreads();
        const size_t qbase = ((size_t)l * BATCH + b0 + t * TB2) * MDIM;
        for (int i = tid; i < TB2 * MDIM / 4; i += 256)
            *reinterpret_cast<float4*>(qtile + i * 4) =
                *reinterpret_cast<const float4*>(g_qs + qbase + i * 4);
        if (tid < TB2) {
            const float* qr = g_qs + qbase + (size_t)tid * MDIM;
            float s = 0.f;
            #pragma unroll
            for (int m = 0; m < MDIM; m++) s += __ldg(qr + m) * ksum_s[m];
            float inv = 1.f / (alpha * s + (float)BATCH);
            sc2[tid] = make_float2(alpha * inv, inv);
        }
        __syncthreads();

        #pragma unroll 2
        for (int bb = 0; bb < TB2 / 2; bb++) {
            const int b = g * (TB2 / 2) + bb;
            const u64* q2 = reinterpret_cast<const u64*>(qtile + b * MDIM);
            u64 a0 = 0ull, a1 = 0ull;
            #pragma unroll
            for (int j = 0; j < 10; j++) {
                a0 = ffma2(q2[j], pa[j], a0);
                a1 = ffma2(q2[j], pb[j], a1);
            }
            float2 f0 = unpack2(a0), f1 = unpack2(a1);
            float2 s2 = sc2[b];
            float o0 = fmaf(f0.x + f0.y, s2.x, fmaf(C0, s2.y, bp0));
            float o1 = fmaf(f1.x + f1.y, s2.x, fmaf(C1, s2.y, bp1));
            size_t ob = ((size_t)(b0 + t * TB2 + b) * LDIM + l) * DDIM + d0;
            *reinterpret_cast<float2*>(out + ob) = make_float2(o0, o1);
        }
    }
}

// ---------------- launch ----------------
extern "C" void kernel_launch(void* const* d_in, const int* in_sizes, int n_in,
                              void* d_out, int out_size) {
    const float* key   = (const float*)d_in[0];
    const float* value = (const float*)d_in[1];
    const float* query = (const float*)d_in[2];
    const float* Wk = (const float*)d_in[3];
    const float* bk = (const float*)d_in[4];
    const float* Wq = (const float*)d_in[5];
    const float* bq = (const float*)d_in[6];
    const float* Wv = (const float*)d_in[7];
    const float* bv = (const float*)d_in[8];
    const float* Wp = (const float*)d_in[9];
    const float* bp = (const float*)d_in[10];
    float* out = (float*)d_out;
    (void)in_sizes; (void)n_in; (void)out_size;

    cudaFuncSetAttribute(k_pass1, cudaFuncAttributeMaxDynamicSharedMemorySize, SM1_BYTES);

    k_init<<<144, 256>>>(Wk, Wq, Wv);
    k_pass1<<<dim3(BATCH / 128, LDIM), 256, SM1_BYTES>>>(key, query, value, bk, bq, bv);
    k_mid<<<LDIM, 256>>>(Wp);
    k_pass2<<<dim3(BATCH / BR2, LDIM), 256>>>(out, bp);
}

// round 9
// speedup vs baseline: 2.8122x; 1.1144x over previous
#include <cuda_runtime.h>
#include <cuda_bf16.h>
#include <cstddef>
#include <cstdint>

#define BATCH 4096
#define LDIM 64
#define DDIM 256
#define MDIM 20
#define BR2 128
#define TB2 64

typedef unsigned long long u64;

// ---------------- helpers ----------------
__device__ __forceinline__ u64 ffma2(u64 a, u64 b, u64 c) {
    u64 d;
    asm("fma.rn.f32x2 %0, %1, %2, %3;" : "=l"(d) : "l"(a), "l"(b), "l"(c));
    return d;
}
__device__ __forceinline__ u64 pack2(float x, float y) {
    u64 r;
    asm("mov.b64 %0, {%1, %2};" : "=l"(r) : "f"(x), "f"(y));
    return r;
}
__device__ __forceinline__ float2 unpack2(u64 a) {
    float2 f;
    asm("mov.b64 {%0, %1}, %2;" : "=f"(f.x), "=f"(f.y) : "l"(a));
    return f;
}
__device__ __forceinline__ void cp16(uint32_t smem_dst, const void* gsrc) {
    asm volatile("cp.async.cg.shared.global [%0], [%1], 16;" :: "r"(smem_dst), "l"(gsrc));
}
#define MMA_BF16(D, A0, A1, A2, A3, B0, B1)                                   \
    asm volatile(                                                             \
        "mma.sync.aligned.m16n8k16.row.col.f32.bf16.bf16.f32 "                \
        "{%0,%1,%2,%3}, {%4,%5,%6,%7}, {%8,%9}, {%0,%1,%2,%3};"               \
        : "+f"((D)[0]), "+f"((D)[1]), "+f"((D)[2]), "+f"((D)[3])              \
        : "r"(A0), "r"(A1), "r"(A2), "r"(A3), "r"(B0), "r"(B1))

// split one float2 into bf16x2 hi + lo words
__device__ __forceinline__ void split2(float2 v, uint32_t& hi, uint32_t& lo) {
    __nv_bfloat162 h = __floats2bfloat162_rn(v.x, v.y);
    hi = *reinterpret_cast<uint32_t*>(&h);
    __nv_bfloat162 l = __floats2bfloat162_rn(v.x - __bfloat162float(h.x),
                                             v.y - __bfloat162float(h.y));
    lo = *reinterpret_cast<uint32_t*>(&l);
}

// ---------------- scratch ----------------
// W packed: [p][split][n=24][k=256] bf16
__device__ __align__(16) __nv_bfloat16 g_Wb2[3 * 2 * 24 * 256];
__device__ float g_qs[(size_t)LDIM * BATCH * MDIM]; // [l][b][m]
__device__ float g_kvs[LDIM * MDIM * MDIM];
__device__ float g_ks_sum[LDIM * MDIM];
__device__ float g_vs_sum[LDIM * MDIM];
__device__ float g_scal[4];                         // sum_q, ssq_q, sum_k, ssq_k
__device__ float g_P[(size_t)LDIM * MDIM * DDIM];
__device__ float g_C[LDIM * DDIM];

// ---------------- kernel 0: weight split/pack + zero reductions ----------------
// grid 144 x 256 = 36,864 threads = one packed element each
__global__ __launch_bounds__(256) void k_init(const float* __restrict__ Wk,
                                              const float* __restrict__ Wq,
                                              const float* __restrict__ Wv) {
    int i = blockIdx.x * 256 + threadIdx.x;
    {
        int k = i & 255;
        int t = i >> 8;
        int n = t % 24; t /= 24;
        int s = t & 1, p = t >> 1;
        const float* W = (p == 0) ? Wk : ((p == 1) ? Wq : Wv);
        float wv = (n < MDIM) ? W[k * MDIM + n] : 0.f;
        __nv_bfloat16 hi = __float2bfloat16(wv);
        g_Wb2[i] = s ? __float2bfloat16(wv - __bfloat162float(hi)) : hi;
    }
    if (i < LDIM * MDIM * MDIM) g_kvs[i] = 0.f;
    if (i < LDIM * MDIM) { g_ks_sum[i] = 0.f; g_vs_sum[i] = 0.f; }
    if (i < 4) g_scal[i] = 0.f;
}

// ---------------- kernel 1: mma.sync projections + reductions ----------------
// 256 thr (8 warps); block = (128 b-rows, one l). 3 proj stages of K=256.
// x loaded DIRECTLY into fragment layout (LDG.64), split hi/lo in regs.
// W cp.async double-buffered: smem rows padded to 132 words (conflict-free).
extern __shared__ float smem1[];

// byte offsets
#define WPROJ_B 25344            // 2 splits x 24 n x 132 words x 4
#define O_WB0 0
#define O_WB1 25344
#define O_KT  50688              // float[128*20]
#define O_VT  60928
#define O_RED 71168              // float[32]
#define SM1_BYTES 71296

__global__ __launch_bounds__(256, 2) void k_pass1(const float* __restrict__ key,
                                                  const float* __restrict__ query,
                                                  const float* __restrict__ value,
                                                  const float* __restrict__ bk,
                                                  const float* __restrict__ bq,
                                                  const float* __restrict__ bv) {
    char* smem = reinterpret_cast<char*>(smem1);
    const int tid = threadIdx.x;
    const int w = tid >> 5, lane = tid & 31;
    const int qr = lane >> 2, qc = lane & 3;
    const int l = blockIdx.x;              // grid swapped: x = l
    const int b0 = blockIdx.y * 128;
    uint32_t sb;
    asm("{ .reg .u64 t; cvta.to.shared.u64 t, %1; cvt.u32.u64 %0, t; }" : "=r"(sb) : "l"(smem));

    float* kt = reinterpret_cast<float*>(smem + O_KT);
    float* vt = reinterpret_cast<float*>(smem + O_VT);
    float* red = reinterpret_cast<float*>(smem + O_RED);

    const float* srcs[3] = {key, query, value};
    const float* biases[3] = {bk, bq, bv};

    // stage W for proj SP into buffer at byte OFF: 1536 cp16 / 256 thr = 6 each
#define STAGE_W(SP, OFF) do {                                                 \
        _Pragma("unroll")                                                     \
        for (int j_ = 0; j_ < 6; j_++) {                                      \
            int idx = j_ * 256 + tid;                                         \
            int s_ = idx / 768, rem = idx % 768;                              \
            int n_ = rem >> 5, c_ = rem & 31;                                 \
            cp16(sb + (OFF) + (uint32_t)((s_ * 3168 + n_ * 132) * 4 + c_ * 16), \
                 reinterpret_cast<const char*>(g_Wb2) +                       \
                 (((SP) * 2 + s_) * 24 + n_) * 512 + c_ * 16);                \
        }                                                                     \
        asm volatile("cp.async.commit_group;");                               \
    } while (0)

    float sk = 0.f, ssk = 0.f, sq = 0.f, ssq = 0.f;
    float acc[3][4];

    STAGE_W(0, O_WB0);

    #pragma unroll 1
    for (int p = 0; p < 3; p++) {
        asm volatile("cp.async.wait_group 0;");
        __syncthreads();            // W(p) visible; all warps done with compute(p-1)
        if (p < 2) STAGE_W(p + 1, (p & 1) ? O_WB0 : O_WB1);

        #pragma unroll
        for (int nt = 0; nt < 3; nt++)
            #pragma unroll
            for (int j = 0; j < 4; j++) acc[nt][j] = 0.f;

        const float* base0 = srcs[p] + ((size_t)(b0 + w * 16 + qr) * LDIM + l) * DDIM;
        const float* base1 = base0 + (size_t)8 * LDIM * DDIM;
        const uint32_t* wh = reinterpret_cast<const uint32_t*>(smem + ((p & 1) ? O_WB1 : O_WB0));
        const uint32_t* wl = wh + 3168;

        #pragma unroll 4
        for (int ks = 0; ks < 16; ks++) {
            const int doff = ks * 16 + 2 * qc;
            float2 x00 = *reinterpret_cast<const float2*>(base0 + doff);
            float2 x01 = *reinterpret_cast<const float2*>(base0 + doff + 8);
            float2 x10 = *reinterpret_cast<const float2*>(base1 + doff);
            float2 x11 = *reinterpret_cast<const float2*>(base1 + doff + 8);
            uint32_t ah0, al0, ah1, al1, ah2, al2, ah3, al3;
            split2(x00, ah0, al0);
            split2(x10, ah1, al1);
            split2(x01, ah2, al2);
            split2(x11, ah3, al3);
            const int kw = ks * 8 + qc;
            #pragma unroll
            for (int nt = 0; nt < 3; nt++) {
                const int bw = (nt * 8 + qr) * 132 + kw;
                uint32_t bh0 = wh[bw], bh1 = wh[bw + 4];
                uint32_t bl0 = wl[bw], bl1 = wl[bw + 4];
                MMA_BF16(acc[nt], ah0, ah1, ah2, ah3, bh0, bh1);
                MMA_BF16(acc[nt], al0, al1, al2, al3, bh0, bh1);
                MMA_BF16(acc[nt], ah0, ah1, ah2, ah3, bl0, bl1);
            }
        }

        // epilogue for proj p
        {
            const float* bias = biases[p];
            const int r0 = w * 16 + qr, r1 = r0 + 8;
            #pragma unroll
            for (int nt = 0; nt < 3; nt++) {
                const int c0 = nt * 8 + qc * 2;
                if (c0 < MDIM) {
                    float bb0 = __ldg(bias + c0), bb1 = __ldg(bias + c0 + 1);
                    float v00 = acc[nt][0] + bb0, v01 = acc[nt][1] + bb1;
                    float v10 = acc[nt][2] + bb0, v11 = acc[nt][3] + bb1;
                    if (p == 0) {
                        kt[r0 * MDIM + c0] = v00; kt[r0 * MDIM + c0 + 1] = v01;
                        kt[r1 * MDIM + c0] = v10; kt[r1 * MDIM + c0 + 1] = v11;
                        sk += v00 + v01 + v10 + v11;
                        ssk += v00 * v00 + v01 * v01 + v10 * v10 + v11 * v11;
                    } else if (p == 1) {
                        sq += v00 + v01 + v10 + v11;
                        ssq += v00 * v00 + v01 * v01 + v10 * v10 + v11 * v11;
                        *reinterpret_cast<float2*>(
                            g_qs + ((size_t)l * BATCH + b0 + r0) * MDIM + c0) = make_float2(v00, v01);
                        *reinterpret_cast<float2*>(
                            g_qs + ((size_t)l * BATCH + b0 + r1) * MDIM + c0) = make_float2(v10, v11);
                    } else {
                        vt[r0 * MDIM + c0] = v00; vt[r0 * MDIM + c0 + 1] = v01;
                        vt[r1 * MDIM + c0] = v10; vt[r1 * MDIM + c0 + 1] = v11;
                    }
                }
            }
        }
    }
#undef STAGE_W
    __syncthreads();

    // ---- kvs partials: warp w reduces rows 16w..16w+15; lanes<20 own m ----
    float* kvp = reinterpret_cast<float*>(smem);   // alias W region: [8][20][20]
    if (lane < MDIM) {
        u64 a[10];
        #pragma unroll
        for (int j = 0; j < 10; j++) a[j] = 0ull;
        #pragma unroll 4
        for (int rr = 0; rr < 16; rr++) {
            int r = w * 16 + rr;
            float km = kt[r * MDIM + lane];
            u64 kk = pack2(km, km);
            const u64* vrow = reinterpret_cast<const u64*>(vt + r * MDIM);
            #pragma unroll
            for (int j = 0; j < 10; j++) a[j] = ffma2(kk, vrow[j], a[j]);
        }
        float2* dst = reinterpret_cast<float2*>(kvp + (w * MDIM + lane) * MDIM);
        #pragma unroll
        for (int j = 0; j < 10; j++) dst[j] = unpack2(a[j]);
    }

    // ---- scalar stats ----
    #pragma unroll
    for (int off = 16; off; off >>= 1) {
        sk  += __shfl_down_sync(0xffffffffu, sk,  off);
        ssk += __shfl_down_sync(0xffffffffu, ssk, off);
        sq  += __shfl_down_sync(0xffffffffu, sq,  off);
        ssq += __shfl_down_sync(0xffffffffu, ssq, off);
    }
    if (lane == 0) { red[w*4+0] = sk; red[w*4+1] = ssk; red[w*4+2] = sq; red[w*4+3] = ssq; }
    __syncthreads();

    if (tid < 4) {
        float s = 0.f;
        #pragma unroll
        for (int ww = 0; ww < 8; ww++) s += red[ww * 4 + tid];
        atomicAdd(&g_scal[(tid + 2) & 3], s);   // 0=sk->2, 1=ssk->3, 2=sq->0, 3=ssq->1
    }
    for (int i = tid; i < MDIM * MDIM; i += 256) {
        float s = 0.f;
        #pragma unroll
        for (int ww = 0; ww < 8; ww++) s += kvp[ww * MDIM * MDIM + i];
        atomicAdd(&g_kvs[l * MDIM * MDIM + i], s);
    }
    if (tid < MDIM) {
        float s1 = 0.f, s2 = 0.f;
        #pragma unroll 8
        for (int r = 0; r < 128; r++) { s1 += kt[r * MDIM + tid]; s2 += vt[r * MDIM + tid]; }
        atomicAdd(&g_ks_sum[l * MDIM + tid], s1);
        atomicAdd(&g_vs_sum[l * MDIM + tid], s2);
    }
}

// ---------------- kernel 2: P[l] = kvs[l] @ Wp, C[l] = vs_sum[l] @ Wp ----------------
__global__ __launch_bounds__(256) void k_mid(const float* __restrict__ Wp) {
    __shared__ float kvs_s[MDIM * MDIM];
    __shared__ float vsum_s[MDIM];
    int l = blockIdx.x, tid = threadIdx.x;
    for (int i = tid; i < MDIM * MDIM; i += 256) kvs_s[i] = g_kvs[l * MDIM * MDIM + i];
    if (tid < MDIM) vsum_s[tid] = g_vs_sum[l * MDIM + tid];
    __syncthreads();
    int d = tid;
    float wp[MDIM];
    #pragma unroll
    for (int m2 = 0; m2 < MDIM; m2++) wp[m2] = __ldg(Wp + m2 * DDIM + d);
    float c = 0.f;
    #pragma unroll
    for (int m2 = 0; m2 < MDIM; m2++) c += vsum_s[m2] * wp[m2];
    g_C[l * DDIM + d] = c;
    #pragma unroll 4
    for (int m = 0; m < MDIM; m++) {
        float s = 0.f;
        #pragma unroll
        for (int m2 = 0; m2 < MDIM; m2++) s += kvs_s[m * MDIM + m2] * wp[m2];
        g_P[((size_t)l * MDIM + m) * DDIM + d] = s;
    }
}

// ---------------- kernel 3: output; thread owns a d-pair, P in regs ----------------
__global__ __launch_bounds__(256) void k_pass2(float* __restrict__ out,
                                               const float* __restrict__ bp) {
    __shared__ __align__(16) float qtile[TB2 * MDIM];
    __shared__ float2 sc2[TB2];
    __shared__ float ksum_s[MDIM];
    const int tid = threadIdx.x;
    const int dp = tid & 127, g = tid >> 7;
    const int d0 = 2 * dp;
    const int l = blockIdx.x, b0 = blockIdx.y * BR2;   // grid swapped

    u64 pa[10], pb[10];
    #pragma unroll
    for (int j = 0; j < 10; j++) {
        const float* P0 = g_P + ((size_t)l * MDIM + 2 * j) * DDIM + d0;
        const float* P1 = g_P + ((size_t)l * MDIM + 2 * j + 1) * DDIM + d0;
        pa[j] = pack2(P0[0], P1[0]);
        pb[j] = pack2(P0[1], P1[1]);
    }
    float C0 = g_C[l * DDIM + d0], C1 = g_C[l * DDIM + d0 + 1];
    float bp0 = __ldg(bp + d0), bp1 = __ldg(bp + d0 + 1);
    if (tid < MDIM) ksum_s[tid] = g_ks_sum[l * MDIM + tid];

    float sqs = g_scal[0], ssq = g_scal[1], sks = g_scal[2], ssk = g_scal[3];
    float alpha = (sqs != 0.f && sks != 0.f) ? rsqrtf(ssq) * rsqrtf(ssk) : 1.f;

    #pragma unroll 1
    for (int t = 0; t < BR2 / TB2; t++) {
        __syncthreads();
        const size_t qbase = ((size_t)l * BATCH + b0 + t * TB2) * MDIM;
        for (int i = tid; i < TB2 * MDIM / 4; i += 256)
            *reinterpret_cast<float4*>(qtile + i * 4) =
                *reinterpret_cast<const float4*>(g_qs + qbase + i * 4);
        if (tid < TB2) {
            const float* qr = g_qs + qbase + (size_t)tid * MDIM;
            float s = 0.f;
            #pragma unroll
            for (int m = 0; m < MDIM; m++) s += __ldg(qr + m) * ksum_s[m];
            float inv = 1.f / (alpha * s + (float)BATCH);
            sc2[tid] = make_float2(alpha * inv, inv);
        }
        __syncthreads();

        #pragma unroll 2
        for (int bb = 0; bb < TB2 / 2; bb++) {
            const int b = g * (TB2 / 2) + bb;
            const u64* q2 = reinterpret_cast<const u64*>(qtile + b * MDIM);
            u64 a0 = 0ull, a1 = 0ull;
            #pragma unroll
            for (int j = 0; j < 10; j++) {
                a0 = ffma2(q2[j], pa[j], a0);
                a1 = ffma2(q2[j], pb[j], a1);
            }
            float2 f0 = unpack2(a0), f1 = unpack2(a1);
            float2 s2 = sc2[b];
            float o0 = fmaf(f0.x + f0.y, s2.x, fmaf(C0, s2.y, bp0));
            float o1 = fmaf(f1.x + f1.y, s2.x, fmaf(C1, s2.y, bp1));
            size_t ob = ((size_t)(b0 + t * TB2 + b) * LDIM + l) * DDIM + d0;
            *reinterpret_cast<float2*>(out + ob) = make_float2(o0, o1);
        }
    }
}

// ---------------- launch ----------------
extern "C" void kernel_launch(void* const* d_in, const int* in_sizes, int n_in,
                              void* d_out, int out_size) {
    const float* key   = (const float*)d_in[0];
    const float* value = (const float*)d_in[1];
    const float* query = (const float*)d_in[2];
    const float* Wk = (const float*)d_in[3];
    const float* bk = (const float*)d_in[4];
    const float* Wq = (const float*)d_in[5];
    const float* bq = (const float*)d_in[6];
    const float* Wv = (const float*)d_in[7];
    const float* bv = (const float*)d_in[8];
    const float* Wp = (const float*)d_in[9];
    const float* bp = (const float*)d_in[10];
    float* out = (float*)d_out;
    (void)in_sizes; (void)n_in; (void)out_size;

    cudaFuncSetAttribute(k_pass1, cudaFuncAttributeMaxDynamicSharedMemorySize, SM1_BYTES);

    k_init<<<144, 256>>>(Wk, Wq, Wv);
    k_pass1<<<dim3(LDIM, BATCH / 128), 256, SM1_BYTES>>>(key, query, value, bk, bq, bv);
    k_mid<<<LDIM, 256>>>(Wp);
    k_pass2<<<dim3(LDIM, BATCH / BR2), 256>>>(out, bp);
}